// round 1
// baseline (speedup 1.0000x reference)
#include <cuda_runtime.h>

#define BB 2
#define DD 160
#define HH 192
#define WW 160
#define NVOX (BB*DD*HH*WW)   // 9,830,400

// Scratch: 5 fields after pass1 (W-sums), 5 fields after pass2 (WH-sums)
__device__ float gA0[NVOX];
__device__ float gA1[NVOX];
__device__ float gA2[NVOX];
__device__ float gA3[NVOX];
__device__ float gA4[NVOX];
__device__ float gB0[NVOX];
__device__ float gB1[NVOX];
__device__ float gB2[NVOX];
__device__ float gB3[NVOX];
__device__ float gB4[NVOX];
__device__ double g_acc;

__global__ void k_zero() { g_acc = 0.0; }

// ---------------------------------------------------------------------------
// Pass 1: along W (contiguous). Fuse target rescale, the 5 pointwise products,
// and the 9-wide window sum via shared memory. One block per (b,d,h) row.
// ---------------------------------------------------------------------------
__global__ void k_pass1(const float* __restrict__ in, const float* __restrict__ tg) {
    __shared__ float sI[WW];
    __shared__ float sT[WW];
    const long base = (long)blockIdx.x * WW;
    const int w = threadIdx.x;
    float iv = in[base + w];
    float tv = (tg[base + w] + 1.0f) * 0.5f;
    sI[w] = iv;
    sT[w] = tv;
    __syncthreads();
    float a0 = 0.f, a1 = 0.f, a2 = 0.f, a3 = 0.f, a4 = 0.f;
#pragma unroll
    for (int j = -4; j <= 4; ++j) {
        int x = w + j;
        if (x >= 0 && x < WW) {
            float a = sI[x], b = sT[x];
            a0 += a;
            a1 += b;
            a2 += a * a;
            a3 += b * b;
            a4 += a * b;
        }
    }
    gA0[base + w] = a0;
    gA1[base + w] = a1;
    gA2[base + w] = a2;
    gA3[base + w] = a3;
    gA4[base + w] = a4;
}

// ---------------------------------------------------------------------------
// Pass 2: along H. Each thread owns one (b,d,w) column chunk of CH2 outputs,
// sliding a 9-deep shift-register window (registers) with a running sum.
// Every element is read exactly once per field. w is fastest -> coalesced.
// ---------------------------------------------------------------------------
#define CH2 64
__global__ void k_pass2() {
    const int NCOL = BB * DD * WW;  // 51200
    int tid = blockIdx.x * blockDim.x + threadIdx.x;
    int col = tid % NCOL;
    int chunk = tid / NCOL;         // 0..2
    int w = col % WW;
    int bd = col / WW;              // b*DD + d
    const long colbase = ((long)bd * HH) * WW + w;
    const int h0 = chunk * CH2;

    float w0[9], w1[9], w2[9], w3[9], w4[9];
#pragma unroll
    for (int i = 0; i < 9; ++i) { w0[i] = w1[i] = w2[i] = w3[i] = w4[i] = 0.f; }
    float r0 = 0.f, r1 = 0.f, r2 = 0.f, r3 = 0.f, r4 = 0.f;

    for (int h = h0 - 8; h < h0 + CH2 + 4; ++h) {
        float v0 = 0.f, v1 = 0.f, v2 = 0.f, v3 = 0.f, v4 = 0.f;
        if (h >= 0 && h < HH) {
            long idx = colbase + (long)h * WW;
            v0 = gA0[idx]; v1 = gA1[idx]; v2 = gA2[idx]; v3 = gA3[idx]; v4 = gA4[idx];
        }
        r0 += v0 - w0[0];
        r1 += v1 - w1[0];
        r2 += v2 - w2[0];
        r3 += v3 - w3[0];
        r4 += v4 - w4[0];
#pragma unroll
        for (int i = 0; i < 8; ++i) {
            w0[i] = w0[i + 1]; w1[i] = w1[i + 1]; w2[i] = w2[i + 1];
            w3[i] = w3[i + 1]; w4[i] = w4[i + 1];
        }
        w0[8] = v0; w1[8] = v1; w2[8] = v2; w3[8] = v3; w4[8] = v4;
        int c = h - 4;
        if (c >= h0 && c < h0 + CH2) {
            long idx = colbase + (long)c * WW;
            gB0[idx] = r0; gB1[idx] = r1; gB2[idx] = r2; gB3[idx] = r3; gB4[idx] = r4;
        }
    }
}

// ---------------------------------------------------------------------------
// Pass 3: along D. Same sliding window, fused with the cc formula and a
// double-precision block reduction + atomicAdd into g_acc.
// ---------------------------------------------------------------------------
#define CH3 40
__global__ void k_pass3() {
    const int NCOL = BB * HH * WW;  // 61440
    int tid = blockIdx.x * blockDim.x + threadIdx.x;
    int col = tid % NCOL;
    int chunk = tid / NCOL;         // 0..3
    int w = col % WW;
    int rest = col / WW;
    int h = rest % HH;
    int b = rest / HH;
    const long colbase = (((long)b * DD) * HH + h) * WW + w;  // d = 0
    const long dstride = (long)HH * WW;
    const int d0 = chunk * CH3;

    float w0[9], w1[9], w2[9], w3[9], w4[9];
#pragma unroll
    for (int i = 0; i < 9; ++i) { w0[i] = w1[i] = w2[i] = w3[i] = w4[i] = 0.f; }
    float r0 = 0.f, r1 = 0.f, r2 = 0.f, r3 = 0.f, r4 = 0.f;

    double acc = 0.0;

    for (int d = d0 - 8; d < d0 + CH3 + 4; ++d) {
        float v0 = 0.f, v1 = 0.f, v2 = 0.f, v3 = 0.f, v4 = 0.f;
        if (d >= 0 && d < DD) {
            long idx = colbase + (long)d * dstride;
            v0 = gB0[idx]; v1 = gB1[idx]; v2 = gB2[idx]; v3 = gB3[idx]; v4 = gB4[idx];
        }
        r0 += v0 - w0[0];
        r1 += v1 - w1[0];
        r2 += v2 - w2[0];
        r3 += v3 - w3[0];
        r4 += v4 - w4[0];
#pragma unroll
        for (int i = 0; i < 8; ++i) {
            w0[i] = w0[i + 1]; w1[i] = w1[i + 1]; w2[i] = w2[i + 1];
            w3[i] = w3[i + 1]; w4[i] = w4[i + 1];
        }
        w0[8] = v0; w1[8] = v1; w2[8] = v2; w3[8] = v3; w4[8] = v4;
        int c = d - 4;
        if (c >= d0 && c < d0 + CH3) {
            // r0=I_sum, r1=T_sum, r2=II_sum, r3=TT_sum, r4=IT_sum
            float Ihat = r0 / 729.0f;
            float That = r1 / 729.0f;
            float cross = r4 - Ihat * r1 - That * r0 + That * Ihat * 729.0f;
            float T_var = r3 - 2.0f * That * r1 + That * That * 729.0f;
            float I_var = r2 - 2.0f * Ihat * r0 + Ihat * Ihat * 729.0f;
            float cc = cross * cross / (T_var * I_var + 1e-5f);
            acc += (double)cc;
        }
    }

    // block reduction (double)
#pragma unroll
    for (int off = 16; off; off >>= 1) acc += __shfl_down_sync(0xffffffffu, acc, off);
    __shared__ double sred[32];
    int lane = threadIdx.x & 31;
    int wid = threadIdx.x >> 5;
    if (lane == 0) sred[wid] = acc;
    __syncthreads();
    if (wid == 0) {
        double a = (lane < (int)(blockDim.x >> 5)) ? sred[lane] : 0.0;
#pragma unroll
        for (int off = 16; off; off >>= 1) a += __shfl_down_sync(0xffffffffu, a, off);
        if (lane == 0) atomicAdd(&g_acc, a);
    }
}

__global__ void k_fin(float* out) {
    out[0] = (float)(-g_acc / (double)NVOX);
}

extern "C" void kernel_launch(void* const* d_in, const int* in_sizes, int n_in,
                              void* d_out, int out_size) {
    const float* in = (const float*)d_in[0];
    const float* tg = (const float*)d_in[1];
    float* out = (float*)d_out;

    k_zero<<<1, 1>>>();
    k_pass1<<<BB * DD * HH, WW>>>(in, tg);
    k_pass2<<<(BB * DD * WW * (HH / CH2)) / 256, 256>>>();
    k_pass3<<<(BB * HH * WW * (DD / CH3)) / 256, 256>>>();
    k_fin<<<1, 1>>>(out);
}

// round 3
// speedup vs baseline: 1.2058x; 1.2058x over previous
#include <cuda_runtime.h>

#define BB 2
#define DD 160
#define HH 192
#define WW 160
#define NVOX (BB*DD*HH*WW)   // 9,830,400
#define KS 729.0f

// Fused scratch: 5 fields, field-major. gA = W-sums, gB = WH-sums.
__device__ float gA[5 * NVOX];
__device__ float gB[5 * NVOX];
__device__ double g_acc;

__global__ void k_zero() { g_acc = 0.0; }

// ---------------------------------------------------------------------------
// Pass 1: along W (contiguous). One block per (b,d,h) row. Shared-memory taps.
// ---------------------------------------------------------------------------
__global__ void k_pass1(const float* __restrict__ in, const float* __restrict__ tg) {
    __shared__ float sI[WW];
    __shared__ float sT[WW];
    const size_t base = (size_t)blockIdx.x * WW;
    const int w = threadIdx.x;
    float iv = in[base + w];
    float tv = (tg[base + w] + 1.0f) * 0.5f;
    sI[w] = iv;
    sT[w] = tv;
    __syncthreads();
    float a0 = 0.f, a1 = 0.f, a2 = 0.f, a3 = 0.f, a4 = 0.f;
#pragma unroll
    for (int j = -4; j <= 4; ++j) {
        int x = w + j;
        if (x >= 0 && x < WW) {
            float a = sI[x], b = sT[x];
            a0 += a;
            a1 += b;
            a2 += a * a;
            a3 += b * b;
            a4 += a * b;
        }
    }
    gA[0 * (size_t)NVOX + base + w] = a0;
    gA[1 * (size_t)NVOX + base + w] = a1;
    gA[2 * (size_t)NVOX + base + w] = a2;
    gA[3 * (size_t)NVOX + base + w] = a3;
    gA[4 * (size_t)NVOX + base + w] = a4;
}

// ---------------------------------------------------------------------------
// Pass 2: along H. ONE FIELD PER THREAD (blockIdx.y = field). Running sum
// with lead/trail loads — no register window. Trail loads hit L2.
// ---------------------------------------------------------------------------
#define CH2 64
#define NCOL2 (BB*DD*WW)     // 51200
__global__ void k_pass2() {
    const int f = blockIdx.y;
    int tid = blockIdx.x * blockDim.x + threadIdx.x;
    int col = tid % NCOL2;
    int chunk = tid / NCOL2;             // 0..2
    int w = col % WW;
    int bd = col / WW;
    const size_t colbase = (size_t)f * NVOX + ((size_t)bd * HH) * WW + w;
    const float* __restrict__ src = gA + colbase;
    float* __restrict__ dst = gB + colbase;
    const int h0 = chunk * CH2;

    float r = 0.f;
#pragma unroll
    for (int j = -4; j <= 4; ++j) {
        int h = h0 + j;
        if (h >= 0 && h < HH) r += src[(size_t)h * WW];
    }
    dst[(size_t)h0 * WW] = r;
#pragma unroll 4
    for (int c = h0 + 1; c < h0 + CH2; ++c) {
        float lead  = (c + 4 < HH) ? src[(size_t)(c + 4) * WW] : 0.f;
        float trail = (c - 5 >= 0) ? src[(size_t)(c - 5) * WW] : 0.f;
        r += lead - trail;
        dst[(size_t)c * WW] = r;
    }
}

// ---------------------------------------------------------------------------
// Pass 3: along D. 5 fields per thread (cc needs all), lead/trail running
// sums (no window), fused cc formula + double block reduction.
// ---------------------------------------------------------------------------
#define CH3 32
#define NCOL3 (BB*HH*WW)     // 61440
__device__ __forceinline__ double cc_val(float r0, float r1, float r2, float r3, float r4) {
    // r0=I_sum r1=T_sum r2=II_sum r3=TT_sum r4=IT_sum
    const float inv = 1.0f / KS;
    float cross = r4 - r0 * r1 * inv;
    float T_var = r3 - r1 * r1 * inv;
    float I_var = r2 - r0 * r0 * inv;
    return (double)(cross * cross / (T_var * I_var + 1e-5f));
}

__global__ void k_pass3() {
    int tid = blockIdx.x * blockDim.x + threadIdx.x;
    int col = tid % NCOL3;
    int chunk = tid / NCOL3;             // 0..4
    int w = col % WW;
    int rest = col / WW;
    int h = rest % HH;
    int b = rest / HH;
    const size_t colbase = (((size_t)b * DD) * HH + h) * WW + w;
    const size_t ds = (size_t)HH * WW;
    const int d0 = chunk * CH3;
    const float* __restrict__ B = gB;

    float r0 = 0.f, r1 = 0.f, r2 = 0.f, r3 = 0.f, r4 = 0.f;
#pragma unroll
    for (int j = -4; j <= 4; ++j) {
        int d = d0 + j;
        if (d >= 0 && d < DD) {
            size_t i = colbase + (size_t)d * ds;
            r0 += B[i];
            r1 += B[i + (size_t)NVOX];
            r2 += B[i + 2 * (size_t)NVOX];
            r3 += B[i + 3 * (size_t)NVOX];
            r4 += B[i + 4 * (size_t)NVOX];
        }
    }
    double acc = cc_val(r0, r1, r2, r3, r4);

#pragma unroll 4
    for (int c = d0 + 1; c < d0 + CH3; ++c) {
        int dl = c + 4, dt = c - 5;
        if (dl < DD) {
            size_t i = colbase + (size_t)dl * ds;
            r0 += B[i];
            r1 += B[i + (size_t)NVOX];
            r2 += B[i + 2 * (size_t)NVOX];
            r3 += B[i + 3 * (size_t)NVOX];
            r4 += B[i + 4 * (size_t)NVOX];
        }
        if (dt >= 0) {
            size_t i = colbase + (size_t)dt * ds;
            r0 -= B[i];
            r1 -= B[i + (size_t)NVOX];
            r2 -= B[i + 2 * (size_t)NVOX];
            r3 -= B[i + 3 * (size_t)NVOX];
            r4 -= B[i + 4 * (size_t)NVOX];
        }
        acc += cc_val(r0, r1, r2, r3, r4);
    }

    // block reduction (double)
#pragma unroll
    for (int off = 16; off; off >>= 1) acc += __shfl_down_sync(0xffffffffu, acc, off);
    __shared__ double sred[32];
    int lane = threadIdx.x & 31;
    int wid = threadIdx.x >> 5;
    if (lane == 0) sred[wid] = acc;
    __syncthreads();
    if (wid == 0) {
        double a = (lane < (int)(blockDim.x >> 5)) ? sred[lane] : 0.0;
#pragma unroll
        for (int off = 16; off; off >>= 1) a += __shfl_down_sync(0xffffffffu, a, off);
        if (lane == 0) atomicAdd(&g_acc, a);
    }
}

__global__ void k_fin(float* out) {
    out[0] = (float)(-g_acc / (double)NVOX);
}

extern "C" void kernel_launch(void* const* d_in, const int* in_sizes, int n_in,
                              void* d_out, int out_size) {
    const float* in = (const float*)d_in[0];
    const float* tg = (const float*)d_in[1];
    float* out = (float*)d_out;

    k_zero<<<1, 1>>>();
    k_pass1<<<BB * DD * HH, WW>>>(in, tg);
    {
        dim3 grid(NCOL2 * (HH / CH2) / 256, 5);
        k_pass2<<<grid, 256>>>();
    }
    k_pass3<<<NCOL3 * (DD / CH3) / 256, 256>>>();
    k_fin<<<1, 1>>>(out);
}

// round 4
// speedup vs baseline: 1.2145x; 1.0072x over previous
#include <cuda_runtime.h>

#define BB 2
#define DD 160
#define HH 192
#define WW 160
#define NVOX (BB*DD*HH*WW)   // 9,830,400
#define KS 729.0f

// Scratch: 5 fields (W-sums), field-major.
__device__ float gA[5 * NVOX];
__device__ double g_acc;

__global__ void k_zero() { g_acc = 0.0; }

// ---------------------------------------------------------------------------
// Pass 1: along W (contiguous). 3 rows per block (480 threads) for occupancy.
// ---------------------------------------------------------------------------
__global__ void k_pass1(const float* __restrict__ in, const float* __restrict__ tg) {
    __shared__ float sI[3][WW];
    __shared__ float sT[3][WW];
    const int w = threadIdx.x;
    const int r = threadIdx.y;
    const size_t row = (size_t)blockIdx.x * 3 + r;
    const size_t base = row * WW;
    float iv = in[base + w];
    float tv = (tg[base + w] + 1.0f) * 0.5f;
    sI[r][w] = iv;
    sT[r][w] = tv;
    __syncthreads();
    float a0 = 0.f, a1 = 0.f, a2 = 0.f, a3 = 0.f, a4 = 0.f;
#pragma unroll
    for (int j = -4; j <= 4; ++j) {
        int x = w + j;
        if (x >= 0 && x < WW) {
            float a = sI[r][x], b = sT[r][x];
            a0 += a;
            a1 += b;
            a2 += a * a;
            a3 += b * b;
            a4 += a * b;
        }
    }
    gA[0 * (size_t)NVOX + base + w] = a0;
    gA[1 * (size_t)NVOX + base + w] = a1;
    gA[2 * (size_t)NVOX + base + w] = a2;
    gA[3 * (size_t)NVOX + base + w] = a3;
    gA[4 * (size_t)NVOX + base + w] = a4;
}

// ---------------------------------------------------------------------------
// Fused pass 2+3: block owns a (HT x WT) tile, walks D. Lead-plane H-sums
// via 9 smem taps; trail H-sums from a thread-private smem ring (9 planes).
// cc formula + double reduction fused at the end of the running D-sum.
// ---------------------------------------------------------------------------
#define WT 16
#define HT 16
#define DCH 80
#define RING 9
#define NT (HT*WT)           // 256 threads

__device__ __forceinline__ double cc_val(float r0, float r1, float r2, float r3, float r4) {
    // r0=I_sum r1=T_sum r2=II_sum r3=TT_sum r4=IT_sum
    const float inv = 1.0f / KS;
    float cross = r4 - r0 * r1 * inv;
    float T_var = r3 - r1 * r1 * inv;
    float I_var = r2 - r0 * r0 * inv;
    return (double)(cross * cross / (T_var * I_var + 1e-5f));
}

__global__ void k_pass23() {
    __shared__ float raw[5][HT + 8][WT];     // lead plane rows (h halo)
    __shared__ float ring[RING][5][NT];      // thread-private Hsum history

    const int tid = threadIdx.x;
    const int tx = tid % WT;
    const int ty = tid / WT;
    const int w0 = blockIdx.x * WT;
    const int h0 = blockIdx.y * HT;
    const int b = blockIdx.z >> 1;
    const int c0 = (blockIdx.z & 1) * DCH;

    const float* __restrict__ A = gA;
    const size_t baseb = ((size_t)b * DD) * HH * WW;

    float r0 = 0.f, r1 = 0.f, r2 = 0.f, r3 = 0.f, r4 = 0.f;
    double acc = 0.0;

    for (int step = 0; step < DCH + 8; ++step) {
        const int dp = c0 - 4 + step;
        const bool din = (dp >= 0 && dp < DD);
        // load raw rows (h0-4 .. h0+HT+3) for plane dp, zero-padded
#pragma unroll
        for (int k = 0; k < 2; ++k) {
            int idx = tid + k * NT;
            if (idx < (HT + 8) * WT) {
                int hr = idx / WT, wq = idx % WT;
                int h = h0 - 4 + hr;
                float v0 = 0.f, v1 = 0.f, v2 = 0.f, v3 = 0.f, v4 = 0.f;
                if (din && h >= 0 && h < HH) {
                    size_t g = baseb + ((size_t)dp * HH + h) * WW + (w0 + wq);
                    v0 = A[g];
                    v1 = A[g + (size_t)NVOX];
                    v2 = A[g + 2 * (size_t)NVOX];
                    v3 = A[g + 3 * (size_t)NVOX];
                    v4 = A[g + 4 * (size_t)NVOX];
                }
                raw[0][hr][wq] = v0;
                raw[1][hr][wq] = v1;
                raw[2][hr][wq] = v2;
                raw[3][hr][wq] = v3;
                raw[4][hr][wq] = v4;
            }
        }
        __syncthreads();

        // H-sum for this thread's (h,w) at plane dp: 9 taps
        float s0 = 0.f, s1 = 0.f, s2 = 0.f, s3 = 0.f, s4 = 0.f;
#pragma unroll
        for (int j = 0; j < 9; ++j) {
            s0 += raw[0][ty + j][tx];
            s1 += raw[1][ty + j][tx];
            s2 += raw[2][ty + j][tx];
            s3 += raw[3][ty + j][tx];
            s4 += raw[4][ty + j][tx];
        }
        const int sl = step % RING;
        ring[sl][0][tid] = s0;
        ring[sl][1][tid] = s1;
        ring[sl][2][tid] = s2;
        ring[sl][3][tid] = s3;
        ring[sl][4][tid] = s4;
        r0 += s0; r1 += s1; r2 += s2; r3 += s3; r4 += s4;

        if (step >= 8) {
            acc += cc_val(r0, r1, r2, r3, r4);
            const int tr = (sl + 1) % RING;   // plane dp-8 = (center-4)
            r0 -= ring[tr][0][tid];
            r1 -= ring[tr][1][tid];
            r2 -= ring[tr][2][tid];
            r3 -= ring[tr][3][tid];
            r4 -= ring[tr][4][tid];
        }
        __syncthreads();
    }

    // block reduction (double)
#pragma unroll
    for (int off = 16; off; off >>= 1) acc += __shfl_down_sync(0xffffffffu, acc, off);
    __shared__ double sred[8];
    int lane = tid & 31;
    int wid = tid >> 5;
    if (lane == 0) sred[wid] = acc;
    __syncthreads();
    if (wid == 0) {
        double a = (lane < 8) ? sred[lane] : 0.0;
#pragma unroll
        for (int off = 4; off; off >>= 1) a += __shfl_down_sync(0xffffffffu, a, off);
        if (lane == 0) atomicAdd(&g_acc, a);
    }
}

__global__ void k_fin(float* out) {
    out[0] = (float)(-g_acc / (double)NVOX);
}

extern "C" void kernel_launch(void* const* d_in, const int* in_sizes, int n_in,
                              void* d_out, int out_size) {
    const float* in = (const float*)d_in[0];
    const float* tg = (const float*)d_in[1];
    float* out = (float*)d_out;

    k_zero<<<1, 1>>>();
    {
        dim3 blk(WW, 3);
        k_pass1<<<(BB * DD * HH) / 3, blk>>>(in, tg);
    }
    {
        dim3 grid(WW / WT, HH / HT, BB * (DD / DCH));   // 10 x 12 x 4 = 480 blocks
        k_pass23<<<grid, NT>>>();
    }
    k_fin<<<1, 1>>>(out);
}

// round 5
// speedup vs baseline: 1.5822x; 1.3028x over previous
#include <cuda_runtime.h>

#define BB 2
#define DD 160
#define HH 192
#define WW 160
#define NVOX (BB*DD*HH*WW)   // 9,830,400
#define KS 729.0f

// Scratch: 5 fields (W-sums), field-major: gA[f][b][d][h][w]
__device__ float gA[5 * NVOX];
__device__ double g_acc;     // static-init 0; k_fin resets after use

// ---------------------------------------------------------------------------
// Pass 1: along W (contiguous). 3 rows per block (480 threads).
// ---------------------------------------------------------------------------
__global__ void k_pass1(const float* __restrict__ in, const float* __restrict__ tg) {
    __shared__ float sI[3][WW];
    __shared__ float sT[3][WW];
    const int w = threadIdx.x;
    const int r = threadIdx.y;
    const size_t base = ((size_t)blockIdx.x * 3 + r) * WW;
    float iv = in[base + w];
    float tv = (tg[base + w] + 1.0f) * 0.5f;
    sI[r][w] = iv;
    sT[r][w] = tv;
    __syncthreads();
    float a0 = 0.f, a1 = 0.f, a2 = 0.f, a3 = 0.f, a4 = 0.f;
#pragma unroll
    for (int j = -4; j <= 4; ++j) {
        int x = w + j;
        if (x >= 0 && x < WW) {
            float a = sI[r][x], b = sT[r][x];
            a0 += a;
            a1 += b;
            a2 += a * a;
            a3 += b * b;
            a4 += a * b;
        }
    }
    gA[0 * (size_t)NVOX + base + w] = a0;
    gA[1 * (size_t)NVOX + base + w] = a1;
    gA[2 * (size_t)NVOX + base + w] = a2;
    gA[3 * (size_t)NVOX + base + w] = a3;
    gA[4 * (size_t)NVOX + base + w] = a4;
}

// ---------------------------------------------------------------------------
// Fused pass 2+3: block = 16 w  x  32 d threads; walks H with per-thread
// running sums (lead/trail LDG, trail hits L2). D-taps via a double-buffered
// 20KB smem tile, ONE sync per step, next step's planes prefetched to regs.
// ---------------------------------------------------------------------------
#define WT 16
#define DT 32
#define DOUT 24            // d outputs per block (lanes 4..27)
#define HCH 96             // H chunk per block
#define NT (WT*DT)         // 512 threads

__device__ __forceinline__ float cc_val(float r0, float r1, float r2, float r3, float r4) {
    const float inv = 1.0f / KS;
    float cross = r4 - r0 * r1 * inv;
    float T_var = r3 - r1 * r1 * inv;
    float I_var = r2 - r0 * r0 * inv;
    return cross * cross / (T_var * I_var + 1e-5f);
}

__global__ __launch_bounds__(NT) void k_pass23() {
    __shared__ float buf[2][5][DT][WT];

    const int tid = threadIdx.x;
    const int tx = tid & (WT - 1);       // w within tile
    const int dl = tid >> 4;             // d lane 0..31
    const int w0 = blockIdx.x * WT;
    const int dtile = blockIdx.y * DOUT; // 0,24,...,144
    const int b = blockIdx.z >> 1;
    const int c0 = (blockIdx.z & 1) * HCH;

    const int d_in = dtile - 4 + dl;
    const bool din = (d_in >= 0 && d_in < DD);
    const int d_out = dtile - 4 + dl;    // same index; output when dl in [4,27]
    const bool dout = (dl >= 4 && dl <= 27 && d_out < DD);

    const float* __restrict__ A = gA;
    // base for (b, d_in, h=0, w0+tx); only used when din
    const size_t gb = din ? ((((size_t)b * DD + d_in) * HH) * WW + w0 + tx) : 0;

    float r0 = 0.f, r1 = 0.f, r2 = 0.f, r3 = 0.f, r4 = 0.f;
    // init: window [c0-5, c0+3]
    if (din) {
#pragma unroll
        for (int h = c0 - 5; h <= c0 + 3; ++h) {
            if (h >= 0) {
                size_t i = gb + (size_t)h * WW;
                r0 += A[i];
                r1 += A[i + (size_t)NVOX];
                r2 += A[i + 2 * (size_t)NVOX];
                r3 += A[i + 3 * (size_t)NVOX];
                r4 += A[i + 4 * (size_t)NVOX];
            }
        }
    }

    float l0, l1, l2, l3, l4, t0, t1, t2, t3, t4;
    // preload lead (h=c0+4) and trail (h=c0-5) for first step
    {
        int hl = c0 + 4, ht = c0 - 5;
        bool vl = din && hl < HH, vt = din && ht >= 0;
        size_t il = gb + (size_t)hl * WW, it = gb + (size_t)ht * WW;
        l0 = vl ? A[il] : 0.f;
        l1 = vl ? A[il + (size_t)NVOX] : 0.f;
        l2 = vl ? A[il + 2 * (size_t)NVOX] : 0.f;
        l3 = vl ? A[il + 3 * (size_t)NVOX] : 0.f;
        l4 = vl ? A[il + 4 * (size_t)NVOX] : 0.f;
        t0 = vt ? A[it] : 0.f;
        t1 = vt ? A[it + (size_t)NVOX] : 0.f;
        t2 = vt ? A[it + 2 * (size_t)NVOX] : 0.f;
        t3 = vt ? A[it + 3 * (size_t)NVOX] : 0.f;
        t4 = vt ? A[it + 4 * (size_t)NVOX] : 0.f;
    }

    float facc = 0.f;
    int p = 0;

    for (int c = c0; c < c0 + HCH; ++c) {
        // advance running H-sum to window [c-4, c+4]
        r0 += l0 - t0;
        r1 += l1 - t1;
        r2 += l2 - t2;
        r3 += l3 - t3;
        r4 += l4 - t4;

        buf[p][0][dl][tx] = r0;
        buf[p][1][dl][tx] = r1;
        buf[p][2][dl][tx] = r2;
        buf[p][3][dl][tx] = r3;
        buf[p][4][dl][tx] = r4;

        // prefetch lead/trail for step c+1 (lead h=c+5, trail h=c-4)
        {
            int hl = c + 5, ht = c - 4;
            bool vl = din && hl < HH, vt = din && ht >= 0;
            size_t il = gb + (size_t)hl * WW, it = gb + (size_t)ht * WW;
            l0 = vl ? A[il] : 0.f;
            l1 = vl ? A[il + (size_t)NVOX] : 0.f;
            l2 = vl ? A[il + 2 * (size_t)NVOX] : 0.f;
            l3 = vl ? A[il + 3 * (size_t)NVOX] : 0.f;
            l4 = vl ? A[il + 4 * (size_t)NVOX] : 0.f;
            t0 = vt ? A[it] : 0.f;
            t1 = vt ? A[it + (size_t)NVOX] : 0.f;
            t2 = vt ? A[it + 2 * (size_t)NVOX] : 0.f;
            t3 = vt ? A[it + 3 * (size_t)NVOX] : 0.f;
            t4 = vt ? A[it + 4 * (size_t)NVOX] : 0.f;
        }

        __syncthreads();

        if (dout) {
            float s0 = 0.f, s1 = 0.f, s2 = 0.f, s3 = 0.f, s4 = 0.f;
#pragma unroll
            for (int j = 0; j < 9; ++j) {
                int dd = dl - 4 + j;
                s0 += buf[p][0][dd][tx];
                s1 += buf[p][1][dd][tx];
                s2 += buf[p][2][dd][tx];
                s3 += buf[p][3][dd][tx];
                s4 += buf[p][4][dd][tx];
            }
            facc += cc_val(s0, s1, s2, s3, s4);
        }
        p ^= 1;
    }

    // block reduction (promote to double)
    double acc = (double)facc;
#pragma unroll
    for (int off = 16; off; off >>= 1) acc += __shfl_down_sync(0xffffffffu, acc, off);
    __shared__ double sred[16];
    int lane = tid & 31;
    int wid = tid >> 5;
    if (lane == 0) sred[wid] = acc;
    __syncthreads();
    if (wid == 0) {
        double a = (lane < 16) ? sred[lane] : 0.0;
#pragma unroll
        for (int off = 8; off; off >>= 1) a += __shfl_down_sync(0xffffffffu, a, off);
        if (lane == 0) atomicAdd(&g_acc, a);
    }
}

__global__ void k_fin(float* out) {
    out[0] = (float)(-g_acc / (double)NVOX);
    g_acc = 0.0;   // reset for next (graph-replayed) launch — deterministic
}

extern "C" void kernel_launch(void* const* d_in, const int* in_sizes, int n_in,
                              void* d_out, int out_size) {
    const float* in = (const float*)d_in[0];
    const float* tg = (const float*)d_in[1];
    float* out = (float*)d_out;

    {
        dim3 blk(WW, 3);
        k_pass1<<<(BB * DD * HH) / 3, blk>>>(in, tg);
    }
    {
        // w tiles x d tiles x (b * h-chunks) = 10 x 7 x 4 = 280 blocks
        dim3 grid(WW / WT, (DD + DOUT - 1) / DOUT, BB * (HH / HCH));
        k_pass23<<<grid, NT>>>();
    }
    k_fin<<<1, 1>>>(out);
}